// round 2
// baseline (speedup 1.0000x reference)
#include <cuda_runtime.h>
#include <math.h>

#define GNUM   100000
#define NNODES 2000000
#define DDIM   300

// ---------------- scratch (static device globals; no allocation) ----------------
static __device__ float  g_moments[22 * GNUM];            // raw per-graph moments
static __device__ float  g_params [25 * GNUM];            // folded per-graph params
static __device__ float  g_h     [(size_t)GNUM * DDIM];   // hidden activations
static __device__ float  g_logits[(size_t)GNUM * DDIM];   // logits
static __device__ double g_acc[2];                        // [0]=pos loss sum, [1]=ce sum

// ---------------- f32x2 packed-FMA helpers (FFMA2 pipe, sm_103a) ----------------
__device__ __forceinline__ unsigned long long pack2(float x) {
    unsigned long long r;
    asm("mov.b64 %0, {%1, %2};" : "=l"(r) : "f"(x), "f"(x));
    return r;
}
__device__ __forceinline__ unsigned long long ffma2(unsigned long long a,
                                                    unsigned long long b,
                                                    unsigned long long c) {
    unsigned long long d;
    asm("fma.rn.f32x2 %0, %1, %2, %3;" : "=l"(d) : "l"(a), "l"(b), "l"(c));
    return d;
}
__device__ __forceinline__ void unpack2(unsigned long long v, float& lo, float& hi) {
    asm("mov.b64 {%0, %1}, %2;" : "=f"(lo), "=f"(hi) : "l"(v));
}

// ---------------- zero scratch accumulators ----------------
__global__ void k_zero() {
    int i = blockIdx.x * blockDim.x + threadIdx.x;
    int stride = gridDim.x * blockDim.x;
    for (int j = i; j < 22 * GNUM; j += stride) g_moments[j] = 0.0f;
    if (i == 0) { g_acc[0] = 0.0; g_acc[1] = 0.0; }
}

// ---------------- pass 1: per-graph raw moments (sorted n2g -> run flush) ----------------
__global__ void k_moments(const int* __restrict__ n2g,
                          const float* __restrict__ pt,   // pos_target [N,3]
                          const float* __restrict__ pp)   // pos_perturbed [N,3]
{
    const int CH = 16;
    int tid = blockIdx.x * blockDim.x + threadIdx.x;
    int start = tid * CH;
    if (start >= NNODES) return;
    int end = min(start + CH, NNODES);

    float a[22];
    int cur = -1;
    for (int n = start; n < end; n++) {
        int g = n2g[n];
        if (g != cur) {
            if (cur >= 0) {
                #pragma unroll
                for (int f = 0; f < 22; f++)
                    atomicAdd(&g_moments[f * GNUM + cur], a[f]);
            }
            cur = g;
            #pragma unroll
            for (int f = 0; f < 22; f++) a[f] = 0.0f;
        }
        float t0 = pt[3*n+0], t1 = pt[3*n+1], t2 = pt[3*n+2];
        float p0 = pp[3*n+0], p1 = pp[3*n+1], p2 = pp[3*n+2];
        a[0] += 1.0f;
        a[1] += t0;  a[2] += t1;  a[3] += t2;
        a[4] += p0;  a[5] += p1;  a[6] += p2;
        a[7]  += p0*p0; a[8]  += p0*p1; a[9]  += p0*p2;
        a[10] += p1*p1; a[11] += p1*p2; a[12] += p2*p2;
        a[13] += t0*p0; a[14] += t0*p1; a[15] += t0*p2;
        a[16] += t1*p0; a[17] += t1*p1; a[18] += t1*p2;
        a[19] += t2*p0; a[20] += t2*p1; a[21] += t2*p2;
    }
    if (cur >= 0) {
        #pragma unroll
        for (int f = 0; f < 22; f++)
            atomicAdd(&g_moments[f * GNUM + cur], a[f]);
    }
}

// ---------------- pass 2: per-graph finalize (centers, ptp/otp, fold scales) ----------------
__global__ void k_graph_finalize(const int* __restrict__ nl,
                                 const float* __restrict__ sigmas)
{
    int g = blockIdx.x * blockDim.x + threadIdx.x;
    if (g >= GNUM) return;

    float m[22];
    #pragma unroll
    for (int f = 0; f < 22; f++) m[f] = g_moments[f * GNUM + g];

    float cnt = fmaxf(m[0], 1.0f);
    float inv = 1.0f / cnt;
    float c[3] = { m[1]*inv, m[2]*inv, m[3]*inv };   // center (target)
    float q[3] = { m[4]*inv, m[5]*inv, m[6]*inv };   // p_center (perturbed)

    // ptp = sum(pp pp^T) - cnt * q q^T   (symmetric)
    float ptp[9];
    ptp[0] = m[7]  - cnt*q[0]*q[0];
    ptp[1] = m[8]  - cnt*q[0]*q[1];
    ptp[2] = m[9]  - cnt*q[0]*q[2];
    ptp[4] = m[10] - cnt*q[1]*q[1];
    ptp[5] = m[11] - cnt*q[1]*q[2];
    ptp[8] = m[12] - cnt*q[2]*q[2];
    ptp[3] = ptp[1]; ptp[6] = ptp[2]; ptp[7] = ptp[5];

    // otp = sum(pos pp^T) - cnt * c q^T
    float otp[9];
    #pragma unroll
    for (int i = 0; i < 3; i++)
        #pragma unroll
        for (int j = 0; j < 3; j++)
            otp[3*i+j] = m[13 + 3*i + j] - cnt * c[i] * q[j];

    float fp = 0.0f, fo = 0.0f;
    #pragma unroll
    for (int k = 0; k < 9; k++) { fp += ptp[k]*ptp[k]; fo += otp[k]*otp[k]; }
    float den = sqrtf(fp) + sqrtf(fo);

    float sg = sigmas[nl[g]];
    float s  = -2.0f / (den * sg);   // score_j = s*(pp_c . ptp[:,j]) - s*(pos_c . otp[:,j])

    g_params[0*GNUM+g] = q[0]; g_params[1*GNUM+g] = q[1]; g_params[2*GNUM+g] = q[2];
    g_params[3*GNUM+g] = c[0]; g_params[4*GNUM+g] = c[1]; g_params[5*GNUM+g] = c[2];
    #pragma unroll
    for (int k = 0; k < 9; k++) g_params[(6 + k) * GNUM + g] = s * ptp[k];
    #pragma unroll
    for (int k = 0; k < 9; k++) g_params[(15 + k) * GNUM + g] = -s * otp[k];
    g_params[24*GNUM+g] = 1.0f / sg;
}

// ---------------- pass 3: per-node loss, global double reduction ----------------
__global__ void k_node_loss(const int* __restrict__ n2g,
                            const float* __restrict__ pt,
                            const float* __restrict__ pp,
                            const float* __restrict__ pn)  // pos_noise_pred
{
    __shared__ double sred[256];
    double local = 0.0;
    int stride = gridDim.x * blockDim.x;
    for (int n = blockIdx.x * blockDim.x + threadIdx.x; n < NNODES; n += stride) {
        int g = n2g[n];
        float q0 = g_params[0*GNUM+g], q1 = g_params[1*GNUM+g], q2 = g_params[2*GNUM+g];
        float c0 = g_params[3*GNUM+g], c1 = g_params[4*GNUM+g], c2 = g_params[5*GNUM+g];
        float invs = g_params[24*GNUM+g];

        float pr0 = pp[3*n+0], pr1 = pp[3*n+1], pr2 = pp[3*n+2];
        float p0 = pr0 - q0, p1 = pr1 - q1, p2 = pr2 - q2;            // pp_c
        float t0 = pt[3*n+0] - c0, t1 = pt[3*n+1] - c1, t2 = pt[3*n+2] - c2;  // pos_c

        float acc = 0.0f;
        #pragma unroll
        for (int j = 0; j < 3; j++) {
            float sc = p0 * g_params[(6 + 0 + j) * GNUM + g]
                     + p1 * g_params[(6 + 3 + j) * GNUM + g]
                     + p2 * g_params[(6 + 6 + j) * GNUM + g]
                     + t0 * g_params[(15 + 0 + j) * GNUM + g]
                     + t1 * g_params[(15 + 3 + j) * GNUM + g]
                     + t2 * g_params[(15 + 6 + j) * GNUM + g];
            float prj = (j == 0) ? pr0 : ((j == 1) ? pr1 : pr2);
            float d = (pn[3*n+j] - prj) * invs - sc;
            acc += d * d;
        }
        local += (double)acc;
    }
    int t = threadIdx.x;
    sred[t] = local;
    __syncthreads();
    for (int o = 128; o > 0; o >>= 1) {
        if (t < o) sred[t] += sred[t + o];
        __syncthreads();
    }
    if (t == 0) atomicAdd(&g_acc[0], sred[0]);
}

// ---------------- GEMM: C = act(A[M,300] @ B[300,300] + bias), packed-f32x2 FFMA ----------------
// MODE 0: A = molecule_repr (arg), C = g_h, act = SiLU
// MODE 1: A = g_h,           C = g_logits, act = identity
template <int MODE>
__global__ void __launch_bounds__(128)
k_gemm(const float* __restrict__ Aarg, const float* __restrict__ B,
       const float* __restrict__ bias, int M)
{
    const float* A = (MODE == 0) ? Aarg : g_h;
    float*       C = (MODE == 0) ? g_h  : g_logits;

    __shared__ __align__(16) float As[20][128];
    __shared__ __align__(16) float Bs[20][64];

    const int t    = threadIdx.x;
    const int row0 = blockIdx.y * 128;
    const int col0 = blockIdx.x * 64;
    const int tx   = t & 7;    // 8 col groups
    const int ty   = t >> 3;   // 16 row groups

    unsigned long long acc[32];
    #pragma unroll
    for (int i = 0; i < 32; i++) acc[i] = 0ull;

    for (int k0 = 0; k0 < 300; k0 += 20) {
        // load A tile 128x20
        #pragma unroll
        for (int i = t; i < 128 * 20; i += 128) {
            int r = i / 20, cc = i % 20;
            int gr = row0 + r;
            float v = (gr < M) ? A[(size_t)gr * 300 + k0 + cc] : 0.0f;
            As[cc][r] = v;
        }
        // load B tile 20x64
        #pragma unroll
        for (int i = t; i < 20 * 64; i += 128) {
            int r = i >> 6, cc = i & 63;
            int gc = col0 + cc;
            float v = (gc < 300) ? B[(k0 + r) * 300 + gc] : 0.0f;
            Bs[r][cc] = v;
        }
        __syncthreads();

        #pragma unroll
        for (int k = 0; k < 20; k++) {
            unsigned long long ap[8], bp[4];
            #pragma unroll
            for (int r = 0; r < 8; r++) ap[r] = pack2(As[k][ty * 8 + r]);
            #pragma unroll
            for (int cidx = 0; cidx < 4; cidx++)
                bp[cidx] = *(const unsigned long long*)(&Bs[k][tx * 8 + 2 * cidx]);
            #pragma unroll
            for (int r = 0; r < 8; r++)
                #pragma unroll
                for (int cidx = 0; cidx < 4; cidx++)
                    acc[r * 4 + cidx] = ffma2(ap[r], bp[cidx], acc[r * 4 + cidx]);
        }
        __syncthreads();
    }

    // epilogue
    #pragma unroll
    for (int r = 0; r < 8; r++) {
        int gr = row0 + ty * 8 + r;
        if (gr >= M) continue;
        #pragma unroll
        for (int cidx = 0; cidx < 4; cidx++) {
            float lo, hi;
            unpack2(acc[r * 4 + cidx], lo, hi);
            int gc = col0 + tx * 8 + 2 * cidx;
            if (gc < 300) {
                float v = lo + bias[gc];
                if (MODE == 0) v = __fdividef(v, 1.0f + __expf(-v));  // SiLU
                C[(size_t)gr * 300 + gc] = v;
            }
            if (gc + 1 < 300) {
                float v = hi + bias[gc + 1];
                if (MODE == 0) v = __fdividef(v, 1.0f + __expf(-v));
                C[(size_t)gr * 300 + gc + 1] = v;
            }
        }
    }
}

// ---------------- CE: per-row logsumexp - logit[target], reduced ----------------
__global__ void k_ce(const int* __restrict__ nl) {
    __shared__ double ssum[8];
    int lane = threadIdx.x & 31;
    int w    = threadIdx.x >> 5;
    int gw   = blockIdx.x * 8 + w;
    int W    = gridDim.x * 8;

    double local = 0.0;
    for (int g = gw; g < GNUM; g += W) {
        const float* row = &g_logits[(size_t)g * 300];
        float v[10];
        float mx = -1e30f;
        #pragma unroll
        for (int i = 0; i < 10; i++) {
            int cidx = lane + 32 * i;
            v[i] = (cidx < 300) ? row[cidx] : -1e30f;
            mx = fmaxf(mx, v[i]);
        }
        #pragma unroll
        for (int o = 16; o > 0; o >>= 1)
            mx = fmaxf(mx, __shfl_xor_sync(0xffffffffu, mx, o));
        float s = 0.0f;
        #pragma unroll
        for (int i = 0; i < 10; i++) s += __expf(v[i] - mx);
        #pragma unroll
        for (int o = 16; o > 0; o >>= 1)
            s += __shfl_xor_sync(0xffffffffu, s, o);
        if (lane == 0) {
            float lt = row[nl[g]];
            local += (double)(mx + logf(s) - lt);
        }
    }
    if (lane == 0) ssum[w] = local;
    __syncthreads();
    if (threadIdx.x == 0) {
        double b = 0.0;
        #pragma unroll
        for (int i = 0; i < 8; i++) b += ssum[i];
        atomicAdd(&g_acc[1], b);
    }
}

// ---------------- finalize output ----------------
__global__ void k_final(float* __restrict__ out) {
    out[0] = (float)(g_acc[0] / (double)GNUM);
    out[1] = (float)(g_acc[1] / (double)GNUM);
}

// ---------------- launch ----------------
extern "C" void kernel_launch(void* const* d_in, const int* in_sizes, int n_in,
                              void* d_out, int out_size) {
    const int* n2g = (const int*)d_in[0];
    // d_in[1] = edge_index (unused, as in reference)
    const int* nl  = (const int*)d_in[2];
    int b = (n_in >= 13) ? 4 : 3;   // skip scalar num_graphs if present
    const float* mol   = (const float*)d_in[b + 0];
    const float* pnoise= (const float*)d_in[b + 1];
    const float* ppert = (const float*)d_in[b + 2];
    const float* ptarg = (const float*)d_in[b + 3];
    const float* W1    = (const float*)d_in[b + 4];
    const float* b1    = (const float*)d_in[b + 5];
    const float* W2    = (const float*)d_in[b + 6];
    const float* b2    = (const float*)d_in[b + 7];
    const float* sig   = (const float*)d_in[b + 8];
    float* out = (float*)d_out;
    (void)in_sizes; (void)out_size;

    k_zero<<<512, 256>>>();

    // Part A: geometry loss
    int mom_threads = (NNODES + 15) / 16;
    k_moments<<<(mom_threads + 255) / 256, 256>>>(n2g, ptarg, ppert);
    k_graph_finalize<<<(GNUM + 255) / 256, 256>>>(nl, sig);
    k_node_loss<<<2048, 256>>>(n2g, ptarg, ppert, pnoise);

    // Part B: MLP head + CE
    dim3 gg((300 + 63) / 64, (GNUM + 127) / 128);
    k_gemm<0><<<gg, 128>>>(mol, W1, b1, GNUM);
    k_gemm<1><<<gg, 128>>>(nullptr, W2, b2, GNUM);
    k_ce<<<1024, 256>>>(nl);

    k_final<<<1, 1>>>(out);
}

// round 7
// speedup vs baseline: 1.8925x; 1.8925x over previous
#include <cuda_runtime.h>
#include <cuda_bf16.h>
#include <math.h>
#include <stdint.h>

#define GNUM   100000
#define NNODES 2000000
#define DDIM   300
#define MPAD   100096          // 782 * 128
#define KP     304             // K padded to 19 chunks of 16
#define NP     320             // N padded to 5 tiles of 64
#define KSTEPS 19              // 304 / 16

// ---------------- scratch (static device globals; no allocation) ----------------
static __device__ float         g_moments[22 * GNUM];
static __device__ float         g_params [25 * GNUM];
static __device__ __nv_bfloat16 g_h_bf16[(size_t)MPAD * KP];   // hidden, bf16, K-padded
static __device__ float         g_logits[(size_t)GNUM * DDIM]; // fp32 logits
static __device__ __nv_bfloat16 g_w1[KP * NP];                 // W1 bf16 [k][n] padded
static __device__ __nv_bfloat16 g_w2[KP * NP];                 // W2 bf16 [k][n] padded
static __device__ double        g_acc[2];                      // [0]=pos sum, [1]=ce sum

// ====================== helpers ======================
__device__ __forceinline__ uint32_t smem_u32(const void* p) {
    uint32_t a;
    asm("{ .reg .u64 t; cvta.to.shared.u64 t, %1; cvt.u32.u64 %0, t; }" : "=r"(a) : "l"(p));
    return a;
}
__device__ __forceinline__ uint32_t pack_bf16x2(float lo, float hi) {
    uint32_t r;
    asm("cvt.rn.bf16x2.f32 %0, %1, %2;" : "=r"(r) : "f"(hi), "f"(lo));
    return r;
}
__device__ __forceinline__ void ldsm_x4(uint32_t& d0, uint32_t& d1, uint32_t& d2,
                                        uint32_t& d3, uint32_t addr) {
    asm volatile("ldmatrix.sync.aligned.m8n8.x4.shared.b16 {%0,%1,%2,%3}, [%4];"
                 : "=r"(d0), "=r"(d1), "=r"(d2), "=r"(d3) : "r"(addr));
}
__device__ __forceinline__ void ldsm_x4_t(uint32_t& d0, uint32_t& d1, uint32_t& d2,
                                          uint32_t& d3, uint32_t addr) {
    asm volatile("ldmatrix.sync.aligned.m8n8.x4.trans.shared.b16 {%0,%1,%2,%3}, [%4];"
                 : "=r"(d0), "=r"(d1), "=r"(d2), "=r"(d3) : "r"(addr));
}
__device__ __forceinline__ void mma_bf16(float* c, const uint32_t* a,
                                         uint32_t b0, uint32_t b1) {
    asm volatile(
        "mma.sync.aligned.m16n8k16.row.col.f32.bf16.bf16.f32 "
        "{%0,%1,%2,%3}, {%4,%5,%6,%7}, {%8,%9}, {%0,%1,%2,%3};"
        : "+f"(c[0]), "+f"(c[1]), "+f"(c[2]), "+f"(c[3])
        : "r"(a[0]), "r"(a[1]), "r"(a[2]), "r"(a[3]), "r"(b0), "r"(b1));
}

// ---------------- zero scratch accumulators ----------------
__global__ void k_zero() {
    int i = blockIdx.x * blockDim.x + threadIdx.x;
    int stride = gridDim.x * blockDim.x;
    for (int j = i; j < 22 * GNUM; j += stride) g_moments[j] = 0.0f;
    if (i == 0) { g_acc[0] = 0.0; g_acc[1] = 0.0; }
}

// ---------------- weight prep: pad + bf16 (no transpose: [k][n]) ----------------
__global__ void k_prep_w(const float* __restrict__ W1, const float* __restrict__ W2) {
    int i = blockIdx.x * blockDim.x + threadIdx.x;
    if (i >= KP * NP) return;
    int k = i / NP, n = i % NP;
    bool in = (k < DDIM && n < DDIM);
    g_w1[i] = __float2bfloat16(in ? W1[k * DDIM + n] : 0.0f);
    g_w2[i] = __float2bfloat16(in ? W2[k * DDIM + n] : 0.0f);
}

// ---------------- pass 1: per-graph raw moments ----------------
__global__ void k_moments(const int* __restrict__ n2g,
                          const float* __restrict__ pt,
                          const float* __restrict__ pp) {
    const int CH = 16;
    int tid = blockIdx.x * blockDim.x + threadIdx.x;
    int start = tid * CH;
    if (start >= NNODES) return;
    int end = min(start + CH, NNODES);

    float a[22];
    int cur = -1;
    for (int n = start; n < end; n++) {
        int g = n2g[n];
        if (g != cur) {
            if (cur >= 0) {
                #pragma unroll
                for (int f = 0; f < 22; f++) atomicAdd(&g_moments[f * GNUM + cur], a[f]);
            }
            cur = g;
            #pragma unroll
            for (int f = 0; f < 22; f++) a[f] = 0.0f;
        }
        float t0 = pt[3*n+0], t1 = pt[3*n+1], t2 = pt[3*n+2];
        float p0 = pp[3*n+0], p1 = pp[3*n+1], p2 = pp[3*n+2];
        a[0] += 1.0f;
        a[1] += t0;  a[2] += t1;  a[3] += t2;
        a[4] += p0;  a[5] += p1;  a[6] += p2;
        a[7]  += p0*p0; a[8]  += p0*p1; a[9]  += p0*p2;
        a[10] += p1*p1; a[11] += p1*p2; a[12] += p2*p2;
        a[13] += t0*p0; a[14] += t0*p1; a[15] += t0*p2;
        a[16] += t1*p0; a[17] += t1*p1; a[18] += t1*p2;
        a[19] += t2*p0; a[20] += t2*p1; a[21] += t2*p2;
    }
    if (cur >= 0) {
        #pragma unroll
        for (int f = 0; f < 22; f++) atomicAdd(&g_moments[f * GNUM + cur], a[f]);
    }
}

// ---------------- pass 2: per-graph finalize ----------------
__global__ void k_graph_finalize(const int* __restrict__ nl,
                                 const float* __restrict__ sigmas) {
    int g = blockIdx.x * blockDim.x + threadIdx.x;
    if (g >= GNUM) return;

    float m[22];
    #pragma unroll
    for (int f = 0; f < 22; f++) m[f] = g_moments[f * GNUM + g];

    float cnt = fmaxf(m[0], 1.0f);
    float inv = 1.0f / cnt;
    float c[3] = { m[1]*inv, m[2]*inv, m[3]*inv };
    float q[3] = { m[4]*inv, m[5]*inv, m[6]*inv };

    float ptp[9];
    ptp[0] = m[7]  - cnt*q[0]*q[0];
    ptp[1] = m[8]  - cnt*q[0]*q[1];
    ptp[2] = m[9]  - cnt*q[0]*q[2];
    ptp[4] = m[10] - cnt*q[1]*q[1];
    ptp[5] = m[11] - cnt*q[1]*q[2];
    ptp[8] = m[12] - cnt*q[2]*q[2];
    ptp[3] = ptp[1]; ptp[6] = ptp[2]; ptp[7] = ptp[5];

    float otp[9];
    #pragma unroll
    for (int i = 0; i < 3; i++)
        #pragma unroll
        for (int j = 0; j < 3; j++)
            otp[3*i+j] = m[13 + 3*i + j] - cnt * c[i] * q[j];

    float fp = 0.0f, fo = 0.0f;
    #pragma unroll
    for (int k = 0; k < 9; k++) { fp += ptp[k]*ptp[k]; fo += otp[k]*otp[k]; }
    float den = sqrtf(fp) + sqrtf(fo);

    float sg = sigmas[nl[g]];
    float s  = -2.0f / (den * sg);

    g_params[0*GNUM+g] = q[0]; g_params[1*GNUM+g] = q[1]; g_params[2*GNUM+g] = q[2];
    g_params[3*GNUM+g] = c[0]; g_params[4*GNUM+g] = c[1]; g_params[5*GNUM+g] = c[2];
    #pragma unroll
    for (int k = 0; k < 9; k++) g_params[(6 + k) * GNUM + g] = s * ptp[k];
    #pragma unroll
    for (int k = 0; k < 9; k++) g_params[(15 + k) * GNUM + g] = -s * otp[k];
    g_params[24*GNUM+g] = 1.0f / sg;
}

// ---------------- pass 3: per-node loss ----------------
__global__ void k_node_loss(const int* __restrict__ n2g,
                            const float* __restrict__ pt,
                            const float* __restrict__ pp,
                            const float* __restrict__ pn) {
    __shared__ double sred[256];
    double local = 0.0;
    int stride = gridDim.x * blockDim.x;
    for (int n = blockIdx.x * blockDim.x + threadIdx.x; n < NNODES; n += stride) {
        int g = n2g[n];
        float q0 = g_params[0*GNUM+g], q1 = g_params[1*GNUM+g], q2 = g_params[2*GNUM+g];
        float c0 = g_params[3*GNUM+g], c1 = g_params[4*GNUM+g], c2 = g_params[5*GNUM+g];
        float invs = g_params[24*GNUM+g];

        float pr0 = pp[3*n+0], pr1 = pp[3*n+1], pr2 = pp[3*n+2];
        float p0 = pr0 - q0, p1 = pr1 - q1, p2 = pr2 - q2;
        float t0 = pt[3*n+0] - c0, t1 = pt[3*n+1] - c1, t2 = pt[3*n+2] - c2;

        float acc = 0.0f;
        #pragma unroll
        for (int j = 0; j < 3; j++) {
            float sc = p0 * g_params[(6 + 0 + j) * GNUM + g]
                     + p1 * g_params[(6 + 3 + j) * GNUM + g]
                     + p2 * g_params[(6 + 6 + j) * GNUM + g]
                     + t0 * g_params[(15 + 0 + j) * GNUM + g]
                     + t1 * g_params[(15 + 3 + j) * GNUM + g]
                     + t2 * g_params[(15 + 6 + j) * GNUM + g];
            float prj = (j == 0) ? pr0 : ((j == 1) ? pr1 : pr2);
            float d = (pn[3*n+j] - prj) * invs - sc;
            acc += d * d;
        }
        local += (double)acc;
    }
    int t = threadIdx.x;
    sred[t] = local;
    __syncthreads();
    for (int o = 128; o > 0; o >>= 1) {
        if (t < o) sred[t] += sred[t + o];
        __syncthreads();
    }
    if (t == 0) atomicAdd(&g_acc[0], sred[0]);
}

// ================= mma.sync bf16 GEMM (family-portable HMMA) =================
// C[M,300] = act(A[M,300] @ W[300,300] + bias)
// MODE 0: A = molecule_repr (fp32 gmem), W = g_w1, SiLU -> g_h_bf16 (bf16, K-padded)
// MODE 1: A = g_h_bf16,                  W = g_w2, identity -> g_logits (fp32)
// CTA: 128 threads / 4 warps. M-tile 128 (A strip resident), 5 N-tiles of 64.
static const int ASTRIDE = 312;                 // bf16 elems per A smem row (pad 304->312)
static const int BSTRIDE = 72;                  // bf16 elems per B smem row (pad 64->72)
static const int SMEM_A  = 0;                   // 128 * 312 * 2 = 79872
static const int SMEM_B  = 128 * ASTRIDE * 2;   // 304 * 72 * 2  = 43776
static const int SMEM_TOT = SMEM_B + KP * BSTRIDE * 2;  // 123648

template <int MODE>
__global__ void __launch_bounds__(128, 1)
k_gemm_mma(const float* __restrict__ Afp32, const float* __restrict__ bias, int M) {
    extern __shared__ char smem[];
    uint32_t sA = smem_u32(smem) + SMEM_A;
    uint32_t sB = smem_u32(smem) + SMEM_B;
    const int tid = threadIdx.x;
    const int w   = tid >> 5;
    const int l   = tid & 31;
    const int row0 = blockIdx.x * 128;

    // ---- load A strip [128 x 304] bf16 into smem ----
    // 152 uint32 (bf16x2) per row
    for (int idx = tid; idx < 128 * 152; idx += 128) {
        int r = idx / 152, kk = idx % 152;
        uint32_t val;
        if (MODE == 0) {
            float lo = 0.0f, hi = 0.0f;
            int gr = row0 + r;
            if (gr < M && kk < 150) {
                float2 v = *(const float2*)(Afp32 + (size_t)gr * DDIM + kk * 2);
                lo = v.x; hi = v.y;
            }
            val = pack_bf16x2(lo, hi);
        } else {
            val = ((const uint32_t*)g_h_bf16)[(size_t)(row0 + r) * 152 + kk];
        }
        *(uint32_t*)(smem + (size_t)r * (ASTRIDE * 2) + kk * 4) = val;
    }

    const __nv_bfloat16* W = (MODE == 0) ? g_w1 : g_w2;

    // per-lane ldmatrix base addresses
    // A: lane -> row (l&15) within 16-row tile, k-chunk (l>>4)*8
    uint32_t a_base0 = sA + (uint32_t)((w * 32 + (l & 15)) * (ASTRIDE * 2)) + ((l >> 4) * 16);
    uint32_t a_base1 = a_base0 + 16 * (ASTRIDE * 2);
    // B: lane -> k-row (l&15), n-chunk (l>>4)*8 within 16-col group
    uint32_t b_base = sB + (uint32_t)((l & 15) * (BSTRIDE * 2)) + ((l >> 4) * 16);

    for (int it = 0; it < 5; it++) {
        const int col0 = it * 64;

        // ---- load B tile [304 x 64] bf16 ----
        __syncthreads();
        {
            const uint32_t* Wsrc = (const uint32_t*)W;
            for (int idx = tid; idx < KP * 32; idx += 128) {
                int r = idx >> 5, cc = idx & 31;
                uint32_t v = Wsrc[r * (NP / 2) + (col0 >> 1) + cc];
                *(uint32_t*)(smem + SMEM_B + (size_t)r * (BSTRIDE * 2) + cc * 4) = v;
            }
        }
        __syncthreads();

        float acc[2][8][4];
        #pragma unroll
        for (int mt = 0; mt < 2; mt++)
            #pragma unroll
            for (int nt = 0; nt < 8; nt++)
                #pragma unroll
                for (int e = 0; e < 4; e++) acc[mt][nt][e] = 0.0f;

        for (int ks = 0; ks < KSTEPS; ks++) {
            const uint32_t koff = (uint32_t)(ks * 32);   // 16 bf16 = 32 bytes
            uint32_t a0[4], a1[4];
            ldsm_x4(a0[0], a0[1], a0[2], a0[3], a_base0 + koff);
            ldsm_x4(a1[0], a1[1], a1[2], a1[3], a_base1 + koff);

            uint32_t b[4][4];
            const uint32_t bk = b_base + (uint32_t)(ks * 16 * (BSTRIDE * 2));
            #pragma unroll
            for (int q = 0; q < 4; q++)
                ldsm_x4_t(b[q][0], b[q][1], b[q][2], b[q][3], bk + q * 32);

            #pragma unroll
            for (int nt = 0; nt < 8; nt++) {
                const int q = nt >> 1, h = (nt & 1) * 2;
                mma_bf16(acc[0][nt], a0, b[q][h], b[q][h + 1]);
                mma_bf16(acc[1][nt], a1, b[q][h], b[q][h + 1]);
            }
        }

        // ---- epilogue ----
        #pragma unroll
        for (int mt = 0; mt < 2; mt++) {
            int r_lo = row0 + w * 32 + mt * 16 + (l >> 2);
            int r_hi = r_lo + 8;
            #pragma unroll
            for (int nt = 0; nt < 8; nt++) {
                int c0 = col0 + nt * 8 + (l & 3) * 2;
                if (c0 >= DDIM) continue;
                float2 bb = *(const float2*)(bias + c0);
                if (MODE == 0) {
                    if (r_lo < M) {
                        float x0 = acc[mt][nt][0] + bb.x;
                        float x1 = acc[mt][nt][1] + bb.y;
                        x0 = __fdividef(x0, 1.0f + __expf(-x0));
                        x1 = __fdividef(x1, 1.0f + __expf(-x1));
                        *(uint32_t*)&g_h_bf16[(size_t)r_lo * KP + c0] = pack_bf16x2(x0, x1);
                    }
                    if (r_hi < M) {
                        float x0 = acc[mt][nt][2] + bb.x;
                        float x1 = acc[mt][nt][3] + bb.y;
                        x0 = __fdividef(x0, 1.0f + __expf(-x0));
                        x1 = __fdividef(x1, 1.0f + __expf(-x1));
                        *(uint32_t*)&g_h_bf16[(size_t)r_hi * KP + c0] = pack_bf16x2(x0, x1);
                    }
                } else {
                    if (r_lo < M) {
                        float* dst = &g_logits[(size_t)r_lo * DDIM + c0];
                        dst[0] = acc[mt][nt][0] + bb.x;
                        dst[1] = acc[mt][nt][1] + bb.y;
                    }
                    if (r_hi < M) {
                        float* dst = &g_logits[(size_t)r_hi * DDIM + c0];
                        dst[0] = acc[mt][nt][2] + bb.x;
                        dst[1] = acc[mt][nt][3] + bb.y;
                    }
                }
            }
        }
    }
}

// ---------------- CE: per-row logsumexp - logit[target] ----------------
__global__ void k_ce(const int* __restrict__ nl) {
    __shared__ double ssum[8];
    int lane = threadIdx.x & 31;
    int w    = threadIdx.x >> 5;
    int gw   = blockIdx.x * 8 + w;
    int W    = gridDim.x * 8;

    double local = 0.0;
    for (int g = gw; g < GNUM; g += W) {
        const float* row = &g_logits[(size_t)g * DDIM];
        float v[10];
        float mx = -1e30f;
        #pragma unroll
        for (int i = 0; i < 10; i++) {
            int cidx = lane + 32 * i;
            v[i] = (cidx < DDIM) ? row[cidx] : -1e30f;
            mx = fmaxf(mx, v[i]);
        }
        #pragma unroll
        for (int o = 16; o > 0; o >>= 1)
            mx = fmaxf(mx, __shfl_xor_sync(0xffffffffu, mx, o));
        float s = 0.0f;
        #pragma unroll
        for (int i = 0; i < 10; i++) s += __expf(v[i] - mx);
        #pragma unroll
        for (int o = 16; o > 0; o >>= 1)
            s += __shfl_xor_sync(0xffffffffu, s, o);
        if (lane == 0) {
            float lt = row[nl[g]];
            local += (double)(mx + logf(s) - lt);
        }
    }
    if (lane == 0) ssum[w] = local;
    __syncthreads();
    if (threadIdx.x == 0) {
        double b = 0.0;
        #pragma unroll
        for (int i = 0; i < 8; i++) b += ssum[i];
        atomicAdd(&g_acc[1], b);
    }
}

// ---------------- finalize output ----------------
__global__ void k_final(float* __restrict__ out) {
    out[0] = (float)(g_acc[0] / (double)GNUM);
    out[1] = (float)(g_acc[1] / (double)GNUM);
}

// ---------------- launch ----------------
extern "C" void kernel_launch(void* const* d_in, const int* in_sizes, int n_in,
                              void* d_out, int out_size) {
    const int* n2g = (const int*)d_in[0];
    // d_in[1] = edge_index (unused)
    const int* nl  = (const int*)d_in[2];
    int b = (n_in >= 13) ? 4 : 3;
    const float* mol    = (const float*)d_in[b + 0];
    const float* pnoise = (const float*)d_in[b + 1];
    const float* ppert  = (const float*)d_in[b + 2];
    const float* ptarg  = (const float*)d_in[b + 3];
    const float* W1     = (const float*)d_in[b + 4];
    const float* b1     = (const float*)d_in[b + 5];
    const float* W2     = (const float*)d_in[b + 6];
    const float* b2     = (const float*)d_in[b + 7];
    const float* sig    = (const float*)d_in[b + 8];
    float* out = (float*)d_out;
    (void)in_sizes; (void)out_size;

    cudaFuncSetAttribute(k_gemm_mma<0>, cudaFuncAttributeMaxDynamicSharedMemorySize, SMEM_TOT);
    cudaFuncSetAttribute(k_gemm_mma<1>, cudaFuncAttributeMaxDynamicSharedMemorySize, SMEM_TOT);

    k_zero<<<512, 256>>>();
    k_prep_w<<<(KP * NP + 255) / 256, 256>>>(W1, W2);

    // Part A: geometry loss
    int mom_threads = (NNODES + 15) / 16;
    k_moments<<<(mom_threads + 255) / 256, 256>>>(n2g, ptarg, ppert);
    k_graph_finalize<<<(GNUM + 255) / 256, 256>>>(nl, sig);
    k_node_loss<<<2048, 256>>>(n2g, ptarg, ppert, pnoise);

    // Part B: MLP head (HMMA) + CE
    int gemm_grid = MPAD / 128;  // 782
    k_gemm_mma<0><<<gemm_grid, 128, SMEM_TOT>>>(mol, b1, GNUM);
    k_gemm_mma<1><<<gemm_grid, 128, SMEM_TOT>>>(nullptr, b2, GNUM);
    k_ce<<<1024, 256>>>(nl);

    k_final<<<1, 1>>>(out);
}